// round 11
// baseline (speedup 1.0000x reference)
#include <cuda_runtime.h>
#include <math.h>
#include <stdint.h>

#define BB 8
#define AA 64
#define HH 128
#define WW 128
#define HX 120
#define WX 120
#define NY (BB*HH*WW)      // 131072
#define NX (BB*AA*HX*WX)   // 7372800
#define NW (AA*9*9)        // 5184
#define TAUF 0.1f
#define NY4 (NY/4)
#define NX4 (NX/4)
#define SV2  73            // conv4 smem stride in f32x2; LDS.64 lane delta 146w ≡ 18 mod 32 (2*odd): conflict-free
#define DSTR 76            // dt smem stride (floats)

// dynamic smem layout for k_conv4 (floats)
#define CONV4_S0   0
#define CONV4_S1   (2 * 40 * SV2)
#define CONV4_STX  (2 * CONV4_S1)
#define CONV4_STG  (CONV4_STX + 2880)
#define CONV4_SMEM ((CONV4_STG + 2880) * 4)   // 69760 bytes

// ------------------------- device state ------------------------------------
__device__ float g_g[NX];
__device__ float g_R[4*NY];           // residual per candidate lane
__device__ float g_Dpart[32*NY];      // plane = cand*8 + group
__device__ float g_pl1[4*1024];
__device__ float g_pf[4*128];
__device__ float g_pl1x[1024];
__device__ float g_cur_cost, g_l1X, g_acc_alpha, g_acc_fid;
__device__ int   g_done, g_rsel;
__device__ unsigned g_count;

// ------------------------- packed f32x2 helpers -----------------------------
__device__ __forceinline__ unsigned long long pk(float lo, float hi)
{
    unsigned long long r;
    asm("mov.b64 %0, {%1, %2};" : "=l"(r) : "f"(lo), "f"(hi));
    return r;
}
__device__ __forceinline__ unsigned long long f2fma(unsigned long long a,
                                                    unsigned long long b,
                                                    unsigned long long c)
{
    unsigned long long d;
    asm("fma.rn.f32x2 %0, %1, %2, %3;" : "=l"(d) : "l"(a), "l"(b), "l"(c));
    return d;
}
__device__ __forceinline__ float2 upk(unsigned long long v)
{
    float2 r;
    asm("mov.b64 {%0, %1}, %2;" : "=f"(r.x), "=f"(r.y) : "l"(v));
    return r;
}
// 8B shared load (forced LDS.64; alignment-safe for float2 arrays)
__device__ __forceinline__ unsigned long long lds64(const float2* p)
{
    unsigned long long v;
    asm volatile("ld.shared.b64 %0, [%1];" : "=l"(v) : "l"((const void*)p));
    return v;
}

// cp.async 4B with zero-fill when sz==0
__device__ __forceinline__ void cpa4(unsigned int daddr, const float* src, unsigned sz)
{
    asm volatile("cp.async.ca.shared.global [%0], [%1], 4, %2;"
                 :: "r"(daddr), "l"(src), "r"(sz));
}
__device__ __forceinline__ void cpa_commit() { asm volatile("cp.async.commit_group;"); }
__device__ __forceinline__ void cpa_wait()   { asm volatile("cp.async.wait_group 0;"); }

__device__ __forceinline__ unsigned int s2u(const void* p)
{
    unsigned int a;
    asm("{ .reg .u64 t; cvta.to.shared.u64 t, %1; cvt.u32.u64 %0, t; }" : "=r"(a) : "l"(p));
    return a;
}

__device__ __forceinline__ float blockReduce(float v, float* sb)
{
    #pragma unroll
    for (int o = 16; o > 0; o >>= 1) v += __shfl_down_sync(0xffffffffu, v, o);
    int lane = threadIdx.x & 31;
    int w    = threadIdx.x >> 5;
    if (lane == 0) sb[w] = v;
    __syncthreads();
    int nw = (blockDim.x + 31) >> 5;
    v = (threadIdx.x < (unsigned)nw) ? sb[threadIdx.x] : 0.f;
    if (w == 0) {
        #pragma unroll
        for (int o = 16; o > 0; o >>= 1) v += __shfl_down_sync(0xffffffffu, v, o);
    }
    __syncthreads();
    return v;
}

__device__ __forceinline__ float softt(float z, float ta)
{
    float t = fabsf(z) - ta;
    return (t > 0.f) ? copysignf(t, z) : 0.f;
}

// ------------------------- quad-candidate D conv + l1 (v2) ------------------
// Input-row-stationary: each thread owns 2 adjacent output rows x 8 cols; each
// 16-wide input-row window loaded once (16 LDS.64, conflict-free) and feeds
// both rows (u=8-t, 9-t) -> ~18 f2fma per 16B loaded (2x round-6 intensity).
// X and g staged via cp.async (zero-filled OOB). 32x64 tiles. Dynamic smem.
// Grid: 512 = 8 batch x 8 tiles x 8 atom-groups (8 atoms). 128 threads.
__global__ void __launch_bounds__(128, 3) k_conv4(const float* __restrict__ X,
                                                  const float* __restrict__ Wd,
                                                  float a0, float a1, float a2, float a3)
{
    if (*((volatile int*)&g_done)) return;

    extern __shared__ __align__(16) float dsm[];
    float2* s[2] = { (float2*)(dsm + CONV4_S0), (float2*)(dsm + CONV4_S1) };
    float* stX = dsm + CONV4_STX;
    float* stG = dsm + CONV4_STG;
    __shared__ float sb[32];

    int bid   = blockIdx.x;
    int group = bid & 7;
    int tile  = (bid >> 3) & 7;
    int b     = bid >> 6;
    int p0 = (tile >> 1) * 32;        // 4 row tiles
    int q0 = (tile & 1) * 64;         // 2 col tiles
    int tid = threadIdx.x;
    int rp  = tid & 15;               // row-pair: output rows 2rp, 2rp+1
    int cg  = tid >> 4;               // 8 col groups of 8

    const float al[4] = {a0, a1, a2, a3};
    const float ta[4] = {TAUF * a0, TAUF * a1, TAUF * a2, TAUF * a3};

    unsigned long long acc[2][2][8];  // [pair][row][col]
    #pragma unroll
    for (int p = 0; p < 2; p++)
        #pragma unroll
        for (int rr = 0; rr < 2; rr++)
            #pragma unroll
            for (int j = 0; j < 8; j++) acc[p][rr][j] = 0ull;
    float l1[4] = {0.f, 0.f, 0.f, 0.f};

    const int g8 = group * 8;
    const size_t plane = (size_t)HX * WX;
    unsigned int stXa = s2u(stX), stGa = s2u(stG);

    // stage first atom (X and g, zero-filled halo/OOB)
    {
        const float* Xa = X   + ((size_t)b * AA + g8) * plane;
        const float* Ga = g_g + ((size_t)b * AA + g8) * plane;
        #pragma unroll
        for (int i = 0; i < 23; i++) {
            int e = tid + i * 128;
            if (e < 2880) {
                int r = e / 72, c0 = e - r * 72;
                int y = p0 - 8 + r, x = q0 - 8 + c0;
                bool in = ((unsigned)y < (unsigned)HX) && ((unsigned)x < (unsigned)WX);
                int o = in ? (y * WX + x) : 0;
                unsigned sz = in ? 4u : 0u;
                cpa4(stXa + 4u * e, Xa + o, sz);
                cpa4(stGa + 4u * e, Ga + o, sz);
            }
        }
        cpa_commit();
    }

    for (int a = g8; a < g8 + 8; ++a) {
        cpa_wait();
        __syncthreads();          // staging visible; s free

        // transform: staged X/g -> interleaved candidate buffers + l1
        #pragma unroll
        for (int i = 0; i < 23; i++) {
            int e = tid + i * 128;
            if (e < 2880) {
                int r = e / 72, c0 = e - r * 72;
                float xv = stX[e];
                float gv = stG[e];
                float v[4];
                #pragma unroll
                for (int c = 0; c < 4; c++) v[c] = softt(fmaf(al[c], gv, xv), ta[c]);
                if (r >= 8 && c0 >= 8) {           // owned region (OOB already zero)
                    #pragma unroll
                    for (int c = 0; c < 4; c++) l1[c] += fabsf(v[c]);
                }
                s[0][r * SV2 + c0] = make_float2(v[0], v[1]);
                s[1][r * SV2 + c0] = make_float2(v[2], v[3]);
            }
        }
        __syncthreads();          // s ready, staging free

        // stage next atom (overlaps compute)
        if (a + 1 < g8 + 8) {
            const float* Xa = X   + ((size_t)b * AA + a + 1) * plane;
            const float* Ga = g_g + ((size_t)b * AA + a + 1) * plane;
            #pragma unroll
            for (int i = 0; i < 23; i++) {
                int e = tid + i * 128;
                if (e < 2880) {
                    int r = e / 72, c0 = e - r * 72;
                    int y = p0 - 8 + r, x = q0 - 8 + c0;
                    bool in = ((unsigned)y < (unsigned)HX) && ((unsigned)x < (unsigned)WX);
                    int o = in ? (y * WX + x) : 0;
                    unsigned sz = in ? 4u : 0u;
                    cpa4(stXa + 4u * e, Xa + o, sz);
                    cpa4(stGa + 4u * e, Ga + o, sz);
                }
            }
            cpa_commit();
        }

        // compute: input rows 2rp+t (t=0..9); u0=8-t feeds out-row0, u1=9-t out-row1
        const float* w = Wd + a * 81;
        #pragma unroll 1
        for (int t = 0; t < 10; ++t) {
            const bool has0 = (t <= 8);
            const bool has1 = (t >= 1);
            const int u0 = 8 - t, u1 = 9 - t;
            unsigned long long w0[9], w1[9];
            if (has0) {
                #pragma unroll
                for (int v = 0; v < 9; ++v) {
                    float wv = __ldg(w + u0 * 9 + v);
                    w0[v] = pk(wv, wv);
                }
            }
            if (has1) {
                #pragma unroll
                for (int v = 0; v < 9; ++v) {
                    float wv = __ldg(w + u1 * 9 + v);
                    w1[v] = pk(wv, wv);
                }
            }
            #pragma unroll
            for (int p = 0; p < 2; p++) {
                const float2* sp = s[p] + (2 * rp + t) * SV2 + cg * 8;
                unsigned long long win2[16];
                #pragma unroll
                for (int i = 0; i < 16; i++) win2[i] = lds64(sp + i);   // LDS.64, conflict-free
                if (has0) {
                    #pragma unroll
                    for (int v = 0; v < 9; ++v)
                        #pragma unroll
                        for (int j = 0; j < 8; ++j)
                            acc[p][0][j] = f2fma(w0[v], win2[8 - v + j], acc[p][0][j]);
                }
                if (has1) {
                    #pragma unroll
                    for (int v = 0; v < 9; ++v)
                        #pragma unroll
                        for (int j = 0; j < 8; ++j)
                            acc[p][1][j] = f2fma(w1[v], win2[8 - v + j], acc[p][1][j]);
                }
            }
        }
    }

    // store partials: rows p0+2rp, p0+2rp+1; cols q0+cg*8..+7
    #pragma unroll
    for (int rr = 0; rr < 2; rr++) {
        size_t off = ((size_t)b * (HH * WW) + (p0 + 2 * rp + rr) * WW + q0 + cg * 8) >> 2;
        #pragma unroll
        for (int p = 0; p < 2; p++) {
            float2 e[8];
            #pragma unroll
            for (int j = 0; j < 8; j++) e[j] = upk(acc[p][rr][j]);
            float4* dpa = (float4*)(g_Dpart) + (size_t)((2 * p) * 8 + group) * NY4 + off;
            dpa[0] = make_float4(e[0].x, e[1].x, e[2].x, e[3].x);
            dpa[1] = make_float4(e[4].x, e[5].x, e[6].x, e[7].x);
            float4* dpb = (float4*)(g_Dpart) + (size_t)((2 * p + 1) * 8 + group) * NY4 + off;
            dpb[0] = make_float4(e[0].y, e[1].y, e[2].y, e[3].y);
            dpb[1] = make_float4(e[4].y, e[5].y, e[6].y, e[7].y);
        }
    }
    #pragma unroll
    for (int c = 0; c < 4; c++) {
        float t = blockReduce(l1[c], sb);
        if (tid == 0) g_pl1[c * 1024 + (bid << 1)] = t;   // 512 blocks -> even slots
    }
}

// ------------------------- scalar single-candidate conv ---------------------
template<int MODE>
__global__ void __launch_bounds__(128, 7) k_conv1(const float* __restrict__ X,
                                                  const float* __restrict__ Wd,
                                                  float a0)
{
    if (MODE && *((volatile int*)&g_done)) return;

    int bid   = blockIdx.x;
    int group = bid & 7;
    int tile  = (bid >> 3) & 15;
    int b     = bid >> 7;
    int p0 = (tile >> 2) * 32;
    int q0 = (tile & 3) * 32;
    int tid = threadIdx.x;
    int row = tid & 31;
    int cg  = tid >> 5;

    __shared__ float s[40 * 41];
    __shared__ float sb[32];

    float acc[8];
    #pragma unroll
    for (int j = 0; j < 8; j++) acc[j] = 0.f;
    float l1 = 0.f;
    const float ta0 = TAUF * a0;

    for (int a = group * 8; a < group * 8 + 8; ++a) {
        const float* Xa = X   + (size_t)(b * AA + a) * (HX * WX);
        const float* Ga = g_g + (size_t)(b * AA + a) * (HX * WX);
        __syncthreads();
        for (int e = tid; e < 1600; e += 128) {
            int r = e / 40, c = e - r * 40;
            int y = p0 - 8 + r, x = q0 - 8 + c;
            float v = 0.f;
            if ((unsigned)y < (unsigned)HX && (unsigned)x < (unsigned)WX) {
                float xv = Xa[y * WX + x];
                if (MODE) v = softt(fmaf(a0, Ga[y * WX + x], xv), ta0);
                else      v = xv;
                if (r >= 8 && c >= 8) l1 += fabsf(v);
            }
            s[r * 41 + c] = v;
        }
        __syncthreads();

        const float* w = Wd + a * 81;
        #pragma unroll
        for (int u = 0; u < 9; ++u) {
            float win[16];
            #pragma unroll
            for (int i = 0; i < 16; i++) win[i] = s[(row + 8 - u) * 41 + cg * 8 + i];
            #pragma unroll
            for (int v = 0; v < 9; ++v) {
                float wv = __ldg(w + u * 9 + v);
                #pragma unroll
                for (int j = 0; j < 8; j++) acc[j] = fmaf(wv, win[8 - v + j], acc[j]);
            }
        }
    }

    size_t off = ((size_t)b * (HH * WW) + (p0 + row) * WW + q0 + cg * 8) >> 2;
    float4* dp = (float4*)(g_Dpart) + (size_t)group * NY4 + off;
    dp[0] = make_float4(acc[0], acc[1], acc[2], acc[3]);
    dp[1] = make_float4(acc[4], acc[5], acc[6], acc[7]);

    float t = blockReduce(l1, sb);
    if (tid == 0) g_pl1[bid] = t;
}

// ------------------------- residual + cost + accept ------------------------
// NC candidates, NP planes/candidate, NB l1-partial slots, ST l1 slot stride.
template<int NC, int NP, int NB, int ST>
__global__ void __launch_bounds__(256) k_red(const float* __restrict__ Y,
                                             int mode, int k,
                                             float a0, float a1, float a2, float a3)
{
    if (mode && *((volatile int*)&g_done)) return;
    int tid = threadIdx.x;
    int i4  = blockIdx.x * 256 + tid;

    const float4* Y4 = (const float4*)Y;
    const float4* DP = (const float4*)g_Dpart;
    float4 y = Y4[i4];

    float fid[NC];
    #pragma unroll
    for (int c = 0; c < NC; c++) {
        float4 d = make_float4(0.f, 0.f, 0.f, 0.f);
        #pragma unroll
        for (int gr = 0; gr < NP; ++gr) {
            float4 p = DP[(size_t)(c * NP + gr) * NY4 + i4];
            d.x += p.x; d.y += p.y; d.z += p.z; d.w += p.w;
        }
        float4 r = make_float4(y.x - d.x, y.y - d.y, y.z - d.z, y.w - d.w);
        ((float4*)(g_R + (size_t)c * NY))[i4] = r;
        fid[c] = r.x * r.x + r.y * r.y + r.z * r.z + r.w * r.w;
    }

    __shared__ float sb[32];
    #pragma unroll
    for (int c = 0; c < NC; c++) {
        float t = blockReduce(fid[c], sb);
        if (tid == 0) g_pf[c * 128 + blockIdx.x] = t;
    }
    __threadfence();
    __shared__ bool last;
    if (tid == 0) last = (atomicAdd(&g_count, 1u) == gridDim.x - 1);
    __syncthreads();
    if (!last) return;

    float f[NC], l[NC];
    #pragma unroll
    for (int c = 0; c < NC; c++) {
        float v = (tid < 128) ? g_pf[c * 128 + tid] : 0.f;
        f[c] = blockReduce(v, sb);
        float lv = 0.f;
        for (int j = tid; j < NB; j += 256) lv += g_pl1[c * 1024 + j * ST];
        l[c] = blockReduce(lv, sb);
    }

    if (tid == 0) {
        g_count = 0;
        if (mode == 0) {
            g_cur_cost = f[0] + TAUF * l[0];
            g_l1X = l[0];
            g_done = 0;
            g_rsel = 0;
        } else {
            const float al[4] = {a0, a1, a2, a3};
            #pragma unroll
            for (int c = 0; c < NC; c++) {
                float cost = f[c] + TAUF * ((k + c == 0) ? g_l1X : l[c]);
                if ((k + c == 16) || cost < g_cur_cost) {
                    g_done = 1; g_rsel = c;
                    g_acc_alpha = al[c]; g_acc_fid = f[c];
                    break;
                }
            }
        }
    }
}

// ------------------------- g = Dt(R) ----------------------------------------
__global__ void __launch_bounds__(256, 2) k_dt(const float* __restrict__ Wd)
{
    int bid = blockIdx.x;
    int ct  = bid & 1;
    int rt  = (bid >> 1) & 3;
    int ag  = (bid >> 3) & 15;
    int b   = bid >> 7;
    int r0 = rt * 32, q0 = ct * 64;
    int tid = threadIdx.x;
    int row = tid & 31, cg = tid >> 5;

    __shared__ __align__(16) float s[40 * DSTR];
    const float* Rb = g_R + (size_t)g_rsel * NY + (size_t)b * (HH * WW);
    for (int e = tid; e < 40 * 72; e += 256) {
        int r = e / 72, c = e - r * 72;
        int rr = r0 + r, cc = q0 + c;
        s[r * DSTR + c] = (rr < HH && cc < WW) ? Rb[rr * WW + cc] : 0.f;
    }
    __syncthreads();

    int y  = r0 + row;
    int x0 = q0 + cg * 8;
    bool valid = (y < HX) && (x0 < WX);
    int abase = ag * 4;

    unsigned long long acc[4][4];
    #pragma unroll
    for (int a = 0; a < 4; a++)
        #pragma unroll
        for (int jp = 0; jp < 4; jp++) acc[a][jp] = 0ull;

    #pragma unroll 1
    for (int i = 0; i < 9; ++i) {
        const float4* sp4 = (const float4*)(s + (row + i) * DSTR + cg * 8);
        float4 A = sp4[0], B4 = sp4[1], C4 = sp4[2], D4 = sp4[3];
        float win[16] = {A.x, A.y, A.z, A.w, B4.x, B4.y, B4.z, B4.w,
                         C4.x, C4.y, C4.z, C4.w, D4.x, D4.y, D4.z, D4.w};
        unsigned long long P[15];
        #pragma unroll
        for (int t = 0; t < 15; t++) P[t] = pk(win[t], win[t + 1]);
        #pragma unroll
        for (int a = 0; a < 4; a++) {
            const float* w = Wd + (abase + a) * 81;
            #pragma unroll
            for (int j = 0; j < 9; ++j) {
                float wv = __ldg(w + j * 9 + i);
                unsigned long long wv2 = pk(wv, wv);
                #pragma unroll
                for (int jp = 0; jp < 4; ++jp)
                    acc[a][jp] = f2fma(wv2, P[j + 2 * jp], acc[a][jp]);
            }
        }
    }
    if (valid) {
        #pragma unroll
        for (int a = 0; a < 4; a++) {
            float* go = g_g + ((size_t)(b * AA + abase + a) * HX + y) * WX + x0;
            #pragma unroll
            for (int jp = 0; jp < 4; jp++) {
                float2 p = upk(acc[a][jp]);
                go[2 * jp] = p.x;
                go[2 * jp + 1] = p.y;
            }
        }
    }
}

// ------------------------- apply accepted step ------------------------------
__global__ void __launch_bounds__(256) k_apply(const float* __restrict__ Xsrc,
                                               float* __restrict__ Xdst)
{
    float alpha = g_acc_alpha;
    float ta = TAUF * alpha;
    float l1 = 0.f;
    int tid = threadIdx.x;
    const float4* Xs4 = (const float4*)Xsrc;
    const float4* G4  = (const float4*)g_g;
    float4* Xd4 = (float4*)Xdst;
    for (int i = blockIdx.x * 256 + tid; i < NX4; i += 1024 * 256) {
        float4 x = Xs4[i];
        float4 g = G4[i];
        float4 o;
        { float z = fmaf(alpha, g.x, x.x); float t = fabsf(z) - ta;
          o.x = (t > 0.f) ? copysignf(t, z) : 0.f; l1 += (t > 0.f) ? t : 0.f; }
        { float z = fmaf(alpha, g.y, x.y); float t = fabsf(z) - ta;
          o.y = (t > 0.f) ? copysignf(t, z) : 0.f; l1 += (t > 0.f) ? t : 0.f; }
        { float z = fmaf(alpha, g.z, x.z); float t = fabsf(z) - ta;
          o.z = (t > 0.f) ? copysignf(t, z) : 0.f; l1 += (t > 0.f) ? t : 0.f; }
        { float z = fmaf(alpha, g.w, x.w); float t = fabsf(z) - ta;
          o.w = (t > 0.f) ? copysignf(t, z) : 0.f; l1 += (t > 0.f) ? t : 0.f; }
        Xd4[i] = o;
    }
    __shared__ float sb[32];
    float tot = blockReduce(l1, sb);
    if (tid == 0) g_pl1x[blockIdx.x] = tot;
    __threadfence();
    __shared__ bool last;
    if (tid == 0) last = (atomicAdd(&g_count, 1u) == gridDim.x - 1);
    __syncthreads();
    if (!last) return;
    float l = 0.f;
    for (int j = tid; j < 1024; j += 256) l += g_pl1x[j];
    l = blockReduce(l, sb);
    if (tid == 0) {
        g_count = 0;
        g_cur_cost = g_acc_fid + TAUF * l;
        g_l1X = l;
        g_done = 0;
    }
}

// ------------------------- host launcher ------------------------------------
extern "C" void kernel_launch(void* const* d_in, const int* in_sizes, int n_in,
                              void* d_out, int out_size)
{
    const float* Y  = nullptr;
    const float* X1 = nullptr;
    const float* Wd = nullptr;
    for (int i = 0; i < n_in; i++) {
        if (in_sizes[i] == NY)      Y  = (const float*)d_in[i];
        else if (in_sizes[i] == NX) X1 = (const float*)d_in[i];
        else if (in_sizes[i] == NW) Wd = (const float*)d_in[i];
    }
    if (!Y)  Y  = (const float*)d_in[0];
    if (!X1) X1 = (const float*)d_in[1];
    if (!Wd) Wd = (const float*)d_in[2];

    float* X = (float*)d_out;

    // opt-in dynamic smem (attribute set, not an allocation; deterministic)
    cudaFuncSetAttribute(k_conv4, cudaFuncAttributeMaxDynamicSharedMemorySize, CONV4_SMEM);

    for (int ls = 0; ls < 4; ++ls) {
        const float* Xin = (ls == 0) ? X1 : X;
        if (ls == 0) {
            k_conv1<0><<<1024, 128>>>(Xin, Wd, 0.f);
            k_red<1, 8, 1024, 1><<<128, 256>>>(Y, 0, -1, 0.f, 0.f, 0.f, 0.f);
        }
        k_dt<<<1024, 256>>>(Wd);
        // quad candidates (conv4 v2: 512 blocks, l1 partials at even slots)
        for (int m = 0; m < 4; ++m) {
            float a0 = ldexpf(1.0f, -(4 * m));
            float a1 = ldexpf(1.0f, -(4 * m + 1));
            float a2 = ldexpf(1.0f, -(4 * m + 2));
            float a3 = ldexpf(1.0f, -(4 * m + 3));
            k_conv4<<<512, 128, CONV4_SMEM>>>(Xin, Wd, a0, a1, a2, a3);
            k_red<4, 8, 512, 2><<<128, 256>>>(Y, 1, 4 * m, a0, a1, a2, a3);
        }
        {
            float a16 = ldexpf(1.0f, -16);
            k_conv1<1><<<1024, 128>>>(Xin, Wd, a16);
            k_red<1, 8, 1024, 1><<<128, 256>>>(Y, 1, 16, a16, 0.f, 0.f, 0.f);
        }
        k_apply<<<1024, 256>>>(Xin, X);
    }
}

// round 12
// speedup vs baseline: 1.3534x; 1.3534x over previous
#include <cuda_runtime.h>
#include <math.h>
#include <stdint.h>

#define BB 8
#define AA 64
#define HH 128
#define WW 128
#define HX 120
#define WX 120
#define NY (BB*HH*WW)      // 131072
#define NX (BB*AA*HX*WX)   // 7372800
#define NW (AA*9*9)        // 5184
#define TAUF 0.1f
#define NY4 (NY/4)
#define NX4 (NX/4)
#define S2   42            // conv smem stride in float2 (84 words, mod32=20: conflict-free)
#define DSTR 76            // dt smem stride (floats)

// ------------------------- device state ------------------------------------
__device__ float g_g[NX];
__device__ float g_R[4*NY];           // residual per candidate lane
__device__ float g_Dpart[32*NY];      // plane = cand*8 + group
__device__ float g_pl1[4*1024];
__device__ float g_pf[4*128];
__device__ float g_pl1x[1024];
__device__ float g_cur_cost, g_l1X, g_acc_alpha, g_acc_fid;
__device__ int   g_done, g_rsel;
__device__ unsigned g_count;

// ------------------------- packed f32x2 helpers -----------------------------
__device__ __forceinline__ unsigned long long pk(float lo, float hi)
{
    unsigned long long r;
    asm("mov.b64 %0, {%1, %2};" : "=l"(r) : "f"(lo), "f"(hi));
    return r;
}
__device__ __forceinline__ unsigned long long f2fma(unsigned long long a,
                                                    unsigned long long b,
                                                    unsigned long long c)
{
    unsigned long long d;
    asm("fma.rn.f32x2 %0, %1, %2, %3;" : "=l"(d) : "l"(a), "l"(b), "l"(c));
    return d;
}
__device__ __forceinline__ float2 upk(unsigned long long v)
{
    float2 r;
    asm("mov.b64 {%0, %1}, %2;" : "=f"(r.x), "=f"(r.y) : "l"(v));
    return r;
}

// cp.async 4B with zero-fill when sz==0
__device__ __forceinline__ void cpa4(unsigned int daddr, const float* src, unsigned sz)
{
    asm volatile("cp.async.ca.shared.global [%0], [%1], 4, %2;"
                 :: "r"(daddr), "l"(src), "r"(sz));
}
__device__ __forceinline__ void cpa_commit() { asm volatile("cp.async.commit_group;"); }
__device__ __forceinline__ void cpa_wait()   { asm volatile("cp.async.wait_group 0;"); }

__device__ __forceinline__ unsigned int s2u(const void* p)
{
    unsigned int a;
    asm("{ .reg .u64 t; cvta.to.shared.u64 t, %1; cvt.u32.u64 %0, t; }" : "=r"(a) : "l"(p));
    return a;
}

__device__ __forceinline__ float blockReduce(float v, float* sb)
{
    #pragma unroll
    for (int o = 16; o > 0; o >>= 1) v += __shfl_down_sync(0xffffffffu, v, o);
    int lane = threadIdx.x & 31;
    int w    = threadIdx.x >> 5;
    if (lane == 0) sb[w] = v;
    __syncthreads();
    int nw = (blockDim.x + 31) >> 5;
    v = (threadIdx.x < (unsigned)nw) ? sb[threadIdx.x] : 0.f;
    if (w == 0) {
        #pragma unroll
        for (int o = 16; o > 0; o >>= 1) v += __shfl_down_sync(0xffffffffu, v, o);
    }
    __syncthreads();
    return v;
}

__device__ __forceinline__ float softt(float z, float ta)
{
    float t = fabsf(z) - ta;
    return (t > 0.f) ? copysignf(t, z) : 0.f;
}

// ------------------------- quad-candidate D conv + l1 -----------------------
// cp.async-pipelined: stage raw X/g tile of atom a+1 during compute of atom a.
// Candidates interleaved pairwise in smem; inner f2fma operand = direct LDS.128.
// Transform phase vectorized 2-wide (pairs never cross rows; STS.128 stores).
// Grid: 1024 = 8 batch x 16 tiles(32x32) x 8 atom-groups(8 atoms). 128 threads.
__global__ void __launch_bounds__(128, 5) k_conv4(const float* __restrict__ X,
                                                  const float* __restrict__ Wd,
                                                  float a0, float a1, float a2, float a3)
{
    if (*((volatile int*)&g_done)) return;

    int bid   = blockIdx.x;
    int group = bid & 7;
    int tile  = (bid >> 3) & 15;
    int b     = bid >> 7;
    int p0 = (tile >> 2) * 32;
    int q0 = (tile & 3) * 32;
    int tid = threadIdx.x;
    int row = tid & 31;
    int cg  = tid >> 5;

    __shared__ __align__(16) float2 s[2][40 * S2];
    __shared__ __align__(16) float stX[1600];
    __shared__ __align__(16) float stG[1600];
    __shared__ float sb[32];

    const float al[4] = {a0, a1, a2, a3};
    const float ta[4] = {TAUF * a0, TAUF * a1, TAUF * a2, TAUF * a3};

    unsigned long long acc[2][8];
    #pragma unroll
    for (int p = 0; p < 2; p++)
        #pragma unroll
        for (int j = 0; j < 8; j++) acc[p][j] = 0ull;
    float l1[4] = {0.f, 0.f, 0.f, 0.f};

    const int g8 = group * 8;
    const size_t plane = (size_t)HX * WX;
    unsigned int stXa = s2u(stX), stGa = s2u(stG);

    // issue stage for first atom
    {
        const float* Xa = X   + ((size_t)b * AA + g8) * plane;
        const float* Ga = g_g + ((size_t)b * AA + g8) * plane;
        #pragma unroll
        for (int i = 0; i < 13; i++) {
            int e = tid + i * 128;
            if (e < 1600) {
                int r = e / 40, c0 = e - r * 40;
                int y = p0 - 8 + r, x = q0 - 8 + c0;
                bool in = ((unsigned)y < (unsigned)HX) && ((unsigned)x < (unsigned)WX);
                int o = in ? (y * WX + x) : 0;
                unsigned sz = in ? 4u : 0u;
                cpa4(stXa + 4u * e, Xa + o, sz);
                cpa4(stGa + 4u * e, Ga + o, sz);
            }
        }
        cpa_commit();
    }

    for (int a = g8; a < g8 + 8; ++a) {
        cpa_wait();
        __syncthreads();          // staging visible to all; s free (prev compute done)

        // transform (2-wide): staging -> interleaved candidate buffers + l1
        // 1600 elems = 800 pairs; row width 40 even -> pairs never cross rows.
        #pragma unroll
        for (int i = 0; i < 7; i++) {
            int ep = tid + i * 128;
            if (ep < 800) {
                int e  = ep << 1;
                int r  = e / 40, c0 = e - r * 40;           // c0 even
                float2 xv = *(const float2*)(stX + e);
                float2 gv = *(const float2*)(stG + e);
                float va[4], vb[4];
                #pragma unroll
                for (int c = 0; c < 4; c++) {
                    va[c] = softt(fmaf(al[c], gv.x, xv.x), ta[c]);
                    vb[c] = softt(fmaf(al[c], gv.y, xv.y), ta[c]);
                }
                if (r >= 8 && c0 >= 8) {                    // both elems owned (c0 even)
                    #pragma unroll
                    for (int c = 0; c < 4; c++) l1[c] += fabsf(va[c]) + fabsf(vb[c]);
                }
                // 16B-aligned: float2 index r*S2+c0 is even
                *(float4*)(s[0] + r * S2 + c0) = make_float4(va[0], va[1], vb[0], vb[1]);
                *(float4*)(s[1] + r * S2 + c0) = make_float4(va[2], va[3], vb[2], vb[3]);
            }
        }
        __syncthreads();          // transform done: s ready, staging free

        // issue stage for next atom (overlaps compute below)
        if (a + 1 < g8 + 8) {
            const float* Xa = X   + ((size_t)b * AA + a + 1) * plane;
            const float* Ga = g_g + ((size_t)b * AA + a + 1) * plane;
            #pragma unroll
            for (int i = 0; i < 13; i++) {
                int e = tid + i * 128;
                if (e < 1600) {
                    int r = e / 40, c0 = e - r * 40;
                    int y = p0 - 8 + r, x = q0 - 8 + c0;
                    bool in = ((unsigned)y < (unsigned)HX) && ((unsigned)x < (unsigned)WX);
                    int o = in ? (y * WX + x) : 0;
                    unsigned sz = in ? 4u : 0u;
                    cpa4(stXa + 4u * e, Xa + o, sz);
                    cpa4(stGa + 4u * e, Ga + o, sz);
                }
            }
            cpa_commit();
        }

        // compute
        const float* w = Wd + a * 81;
        #pragma unroll 1
        for (int u = 0; u < 9; ++u) {
            unsigned long long wv2[9];
            #pragma unroll
            for (int v = 0; v < 9; ++v) {
                float wv = __ldg(w + u * 9 + v);
                wv2[v] = pk(wv, wv);
            }
            #pragma unroll
            for (int p = 0; p < 2; p++) {
                const ulonglong2* sp = (const ulonglong2*)(s[p] + (row + 8 - u) * S2 + cg * 8);
                unsigned long long win2[16];
                #pragma unroll
                for (int i = 0; i < 8; i++) {
                    ulonglong2 q = sp[i];
                    win2[2 * i]     = q.x;
                    win2[2 * i + 1] = q.y;
                }
                #pragma unroll
                for (int v = 0; v < 9; ++v) {
                    #pragma unroll
                    for (int j = 0; j < 8; ++j)
                        acc[p][j] = f2fma(wv2[v], win2[8 - v + j], acc[p][j]);
                }
            }
        }
    }

    size_t off = ((size_t)b * (HH * WW) + (p0 + row) * WW + q0 + cg * 8) >> 2;
    #pragma unroll
    for (int p = 0; p < 2; p++) {
        float2 e[8];
        #pragma unroll
        for (int j = 0; j < 8; j++) e[j] = upk(acc[p][j]);
        float4* dpa = (float4*)(g_Dpart) + (size_t)((2 * p) * 8 + group) * NY4 + off;
        dpa[0] = make_float4(e[0].x, e[1].x, e[2].x, e[3].x);
        dpa[1] = make_float4(e[4].x, e[5].x, e[6].x, e[7].x);
        float4* dpb = (float4*)(g_Dpart) + (size_t)((2 * p + 1) * 8 + group) * NY4 + off;
        dpb[0] = make_float4(e[0].y, e[1].y, e[2].y, e[3].y);
        dpb[1] = make_float4(e[4].y, e[5].y, e[6].y, e[7].y);
    }
    #pragma unroll
    for (int c = 0; c < 4; c++) {
        float t = blockReduce(l1[c], sb);
        if (tid == 0) g_pl1[c * 1024 + bid] = t;
    }
}

// ------------------------- scalar single-candidate conv ---------------------
template<int MODE>
__global__ void __launch_bounds__(128, 7) k_conv1(const float* __restrict__ X,
                                                  const float* __restrict__ Wd,
                                                  float a0)
{
    if (MODE && *((volatile int*)&g_done)) return;

    int bid   = blockIdx.x;
    int group = bid & 7;
    int tile  = (bid >> 3) & 15;
    int b     = bid >> 7;
    int p0 = (tile >> 2) * 32;
    int q0 = (tile & 3) * 32;
    int tid = threadIdx.x;
    int row = tid & 31;
    int cg  = tid >> 5;

    __shared__ float s[40 * 41];
    __shared__ float sb[32];

    float acc[8];
    #pragma unroll
    for (int j = 0; j < 8; j++) acc[j] = 0.f;
    float l1 = 0.f;
    const float ta0 = TAUF * a0;

    for (int a = group * 8; a < group * 8 + 8; ++a) {
        const float* Xa = X   + (size_t)(b * AA + a) * (HX * WX);
        const float* Ga = g_g + (size_t)(b * AA + a) * (HX * WX);
        __syncthreads();
        for (int e = tid; e < 1600; e += 128) {
            int r = e / 40, c = e - r * 40;
            int y = p0 - 8 + r, x = q0 - 8 + c;
            float v = 0.f;
            if ((unsigned)y < (unsigned)HX && (unsigned)x < (unsigned)WX) {
                float xv = Xa[y * WX + x];
                if (MODE) v = softt(fmaf(a0, Ga[y * WX + x], xv), ta0);
                else      v = xv;
                if (r >= 8 && c >= 8) l1 += fabsf(v);
            }
            s[r * 41 + c] = v;
        }
        __syncthreads();

        const float* w = Wd + a * 81;
        #pragma unroll
        for (int u = 0; u < 9; ++u) {
            float win[16];
            #pragma unroll
            for (int i = 0; i < 16; i++) win[i] = s[(row + 8 - u) * 41 + cg * 8 + i];
            #pragma unroll
            for (int v = 0; v < 9; ++v) {
                float wv = __ldg(w + u * 9 + v);
                #pragma unroll
                for (int j = 0; j < 8; j++) acc[j] = fmaf(wv, win[8 - v + j], acc[j]);
            }
        }
    }

    size_t off = ((size_t)b * (HH * WW) + (p0 + row) * WW + q0 + cg * 8) >> 2;
    float4* dp = (float4*)(g_Dpart) + (size_t)group * NY4 + off;
    dp[0] = make_float4(acc[0], acc[1], acc[2], acc[3]);
    dp[1] = make_float4(acc[4], acc[5], acc[6], acc[7]);

    float t = blockReduce(l1, sb);
    if (tid == 0) g_pl1[bid] = t;
}

// ------------------------- residual + cost + accept ------------------------
template<int NC>
__global__ void __launch_bounds__(256) k_red(const float* __restrict__ Y,
                                             int mode, int k,
                                             float a0, float a1, float a2, float a3)
{
    if (mode && *((volatile int*)&g_done)) return;
    int tid = threadIdx.x;
    int i4  = blockIdx.x * 256 + tid;

    const float4* Y4 = (const float4*)Y;
    const float4* DP = (const float4*)g_Dpart;
    float4 y = Y4[i4];

    float fid[NC];
    #pragma unroll
    for (int c = 0; c < NC; c++) {
        float4 d = make_float4(0.f, 0.f, 0.f, 0.f);
        #pragma unroll
        for (int gr = 0; gr < 8; ++gr) {
            float4 p = DP[(size_t)(c * 8 + gr) * NY4 + i4];
            d.x += p.x; d.y += p.y; d.z += p.z; d.w += p.w;
        }
        float4 r = make_float4(y.x - d.x, y.y - d.y, y.z - d.z, y.w - d.w);
        ((float4*)(g_R + (size_t)c * NY))[i4] = r;
        fid[c] = r.x * r.x + r.y * r.y + r.z * r.z + r.w * r.w;
    }

    __shared__ float sb[32];
    #pragma unroll
    for (int c = 0; c < NC; c++) {
        float t = blockReduce(fid[c], sb);
        if (tid == 0) g_pf[c * 128 + blockIdx.x] = t;
    }
    __threadfence();
    __shared__ bool last;
    if (tid == 0) last = (atomicAdd(&g_count, 1u) == gridDim.x - 1);
    __syncthreads();
    if (!last) return;

    float f[NC], l[NC];
    #pragma unroll
    for (int c = 0; c < NC; c++) {
        float v = (tid < 128) ? g_pf[c * 128 + tid] : 0.f;
        f[c] = blockReduce(v, sb);
        float lv = 0.f;
        for (int j = tid; j < 1024; j += 256) lv += g_pl1[c * 1024 + j];
        l[c] = blockReduce(lv, sb);
    }

    if (tid == 0) {
        g_count = 0;
        if (mode == 0) {
            g_cur_cost = f[0] + TAUF * l[0];
            g_l1X = l[0];
            g_done = 0;
            g_rsel = 0;
        } else {
            const float al[4] = {a0, a1, a2, a3};
            #pragma unroll
            for (int c = 0; c < NC; c++) {
                float cost = f[c] + TAUF * ((k + c == 0) ? g_l1X : l[c]);
                if ((k + c == 16) || cost < g_cur_cost) {
                    g_done = 1; g_rsel = c;
                    g_acc_alpha = al[c]; g_acc_fid = f[c];
                    break;
                }
            }
        }
    }
}

// ------------------------- g = Dt(R) ----------------------------------------
__global__ void __launch_bounds__(256, 2) k_dt(const float* __restrict__ Wd)
{
    int bid = blockIdx.x;
    int ct  = bid & 1;
    int rt  = (bid >> 1) & 3;
    int ag  = (bid >> 3) & 15;
    int b   = bid >> 7;
    int r0 = rt * 32, q0 = ct * 64;
    int tid = threadIdx.x;
    int row = tid & 31, cg = tid >> 5;

    __shared__ __align__(16) float s[40 * DSTR];
    const float* Rb = g_R + (size_t)g_rsel * NY + (size_t)b * (HH * WW);
    for (int e = tid; e < 40 * 72; e += 256) {
        int r = e / 72, c = e - r * 72;
        int rr = r0 + r, cc = q0 + c;
        s[r * DSTR + c] = (rr < HH && cc < WW) ? Rb[rr * WW + cc] : 0.f;
    }
    __syncthreads();

    int y  = r0 + row;
    int x0 = q0 + cg * 8;
    bool valid = (y < HX) && (x0 < WX);
    int abase = ag * 4;

    unsigned long long acc[4][4];
    #pragma unroll
    for (int a = 0; a < 4; a++)
        #pragma unroll
        for (int jp = 0; jp < 4; jp++) acc[a][jp] = 0ull;

    #pragma unroll 1
    for (int i = 0; i < 9; ++i) {
        const float4* sp4 = (const float4*)(s + (row + i) * DSTR + cg * 8);
        float4 A = sp4[0], B4 = sp4[1], C4 = sp4[2], D4 = sp4[3];
        float win[16] = {A.x, A.y, A.z, A.w, B4.x, B4.y, B4.z, B4.w,
                         C4.x, C4.y, C4.z, C4.w, D4.x, D4.y, D4.z, D4.w};
        unsigned long long P[15];
        #pragma unroll
        for (int t = 0; t < 15; t++) P[t] = pk(win[t], win[t + 1]);
        #pragma unroll
        for (int a = 0; a < 4; a++) {
            const float* w = Wd + (abase + a) * 81;
            #pragma unroll
            for (int j = 0; j < 9; ++j) {
                float wv = __ldg(w + j * 9 + i);
                unsigned long long wv2 = pk(wv, wv);
                #pragma unroll
                for (int jp = 0; jp < 4; ++jp)
                    acc[a][jp] = f2fma(wv2, P[j + 2 * jp], acc[a][jp]);
            }
        }
    }
    if (valid) {
        #pragma unroll
        for (int a = 0; a < 4; a++) {
            float* go = g_g + ((size_t)(b * AA + abase + a) * HX + y) * WX + x0;
            #pragma unroll
            for (int jp = 0; jp < 4; jp++) {
                float2 p = upk(acc[a][jp]);
                go[2 * jp] = p.x;
                go[2 * jp + 1] = p.y;
            }
        }
    }
}

// ------------------------- apply accepted step ------------------------------
__global__ void __launch_bounds__(256) k_apply(const float* __restrict__ Xsrc,
                                               float* __restrict__ Xdst)
{
    float alpha = g_acc_alpha;
    float ta = TAUF * alpha;
    float l1 = 0.f;
    int tid = threadIdx.x;
    const float4* Xs4 = (const float4*)Xsrc;
    const float4* G4  = (const float4*)g_g;
    float4* Xd4 = (float4*)Xdst;
    for (int i = blockIdx.x * 256 + tid; i < NX4; i += 1024 * 256) {
        float4 x = Xs4[i];
        float4 g = G4[i];
        float4 o;
        { float z = fmaf(alpha, g.x, x.x); float t = fabsf(z) - ta;
          o.x = (t > 0.f) ? copysignf(t, z) : 0.f; l1 += (t > 0.f) ? t : 0.f; }
        { float z = fmaf(alpha, g.y, x.y); float t = fabsf(z) - ta;
          o.y = (t > 0.f) ? copysignf(t, z) : 0.f; l1 += (t > 0.f) ? t : 0.f; }
        { float z = fmaf(alpha, g.z, x.z); float t = fabsf(z) - ta;
          o.z = (t > 0.f) ? copysignf(t, z) : 0.f; l1 += (t > 0.f) ? t : 0.f; }
        { float z = fmaf(alpha, g.w, x.w); float t = fabsf(z) - ta;
          o.w = (t > 0.f) ? copysignf(t, z) : 0.f; l1 += (t > 0.f) ? t : 0.f; }
        Xd4[i] = o;
    }
    __shared__ float sb[32];
    float tot = blockReduce(l1, sb);
    if (tid == 0) g_pl1x[blockIdx.x] = tot;
    __threadfence();
    __shared__ bool last;
    if (tid == 0) last = (atomicAdd(&g_count, 1u) == gridDim.x - 1);
    __syncthreads();
    if (!last) return;
    float l = 0.f;
    for (int j = tid; j < 1024; j += 256) l += g_pl1x[j];
    l = blockReduce(l, sb);
    if (tid == 0) {
        g_count = 0;
        g_cur_cost = g_acc_fid + TAUF * l;
        g_l1X = l;
        g_done = 0;
    }
}

// ------------------------- host launcher ------------------------------------
extern "C" void kernel_launch(void* const* d_in, const int* in_sizes, int n_in,
                              void* d_out, int out_size)
{
    const float* Y  = nullptr;
    const float* X1 = nullptr;
    const float* Wd = nullptr;
    for (int i = 0; i < n_in; i++) {
        if (in_sizes[i] == NY)      Y  = (const float*)d_in[i];
        else if (in_sizes[i] == NX) X1 = (const float*)d_in[i];
        else if (in_sizes[i] == NW) Wd = (const float*)d_in[i];
    }
    if (!Y)  Y  = (const float*)d_in[0];
    if (!X1) X1 = (const float*)d_in[1];
    if (!Wd) Wd = (const float*)d_in[2];

    float* X = (float*)d_out;

    for (int ls = 0; ls < 4; ++ls) {
        const float* Xin = (ls == 0) ? X1 : X;
        if (ls == 0) {
            k_conv1<0><<<1024, 128>>>(Xin, Wd, 0.f);
            k_red<1><<<128, 256>>>(Y, 0, -1, 0.f, 0.f, 0.f, 0.f);
        }
        k_dt<<<1024, 256>>>(Wd);
        for (int m = 0; m < 4; ++m) {
            float a0 = ldexpf(1.0f, -(4 * m));
            float a1 = ldexpf(1.0f, -(4 * m + 1));
            float a2 = ldexpf(1.0f, -(4 * m + 2));
            float a3 = ldexpf(1.0f, -(4 * m + 3));
            k_conv4<<<1024, 128>>>(Xin, Wd, a0, a1, a2, a3);
            k_red<4><<<128, 256>>>(Y, 1, 4 * m, a0, a1, a2, a3);
        }
        {
            float a16 = ldexpf(1.0f, -16);
            k_conv1<1><<<1024, 128>>>(Xin, Wd, a16);
            k_red<1><<<128, 256>>>(Y, 1, 16, a16, 0.f, 0.f, 0.f);
        }
        k_apply<<<1024, 256>>>(Xin, X);
    }
}